// round 1
// baseline (speedup 1.0000x reference)
#include <cuda_runtime.h>
#include <cstdint>

// Problem constants
#define BATCH   4
#define SEQ     4096
#define DMODEL  2048
#define TOKENS  (BATCH * SEQ)     // 16384
#define NC      33                // 16 q + 16 k + 1 w
#define DSPLIT  4
#define DCHUNK  (DMODEL / DSPLIT) // 512

typedef unsigned long long u64;

// Scratch (static device globals: no dynamic allocation allowed)
__device__ float g_part[DSPLIT * TOKENS * NC];   // ~8.7 MB
__device__ float g_q[TOKENS * 16];
__device__ float g_k[TOKENS * 16];
__device__ float g_w[TOKENS];

// ---- packed f32x2 helpers (FFMA2 path, PTX-only per sm_103a) ----
__device__ __forceinline__ u64 pack2(float lo, float hi) {
    u64 r; asm("mov.b64 %0, {%1, %2};" : "=l"(r) : "f"(lo), "f"(hi)); return r;
}
__device__ __forceinline__ void unpack2(u64 v, float& lo, float& hi) {
    asm("mov.b64 {%0, %1}, %2;" : "=f"(lo), "=f"(hi) : "l"(v));
}
__device__ __forceinline__ u64 fma2(u64 a, u64 b, u64 c) {
    u64 d; asm("fma.rn.f32x2 %0, %1, %2, %3;" : "=l"(d) : "l"(a), "l"(b), "l"(c)); return d;
}

// ============================================================================
// Kernel 1: projection. Computes partial (over a D chunk) of x @ [Wq|Wk|Ww].
// Grid: (64 token-blocks, DSPLIT). Block: 128 threads, 256 tokens (2/thread).
// ============================================================================
__global__ __launch_bounds__(128)
void proj_kernel(const float* __restrict__ x,
                 const float* __restrict__ Wq,
                 const float* __restrict__ Wk,
                 const float* __restrict__ Ww)
{
    __shared__ float xs[32][257];   // [d-sub][token], padded: conflict-free
    __shared__ float ws[32][34];    // [d-sub][33 cols], 8B-aligned rows (136B)

    const int tid   = threadIdx.x;
    const int tok0  = blockIdx.x * 256;
    const int dbase = blockIdx.y * DCHUNK;

    u64 accA[16], accB[16];
    float accwA = 0.f, accwB = 0.f;
    #pragma unroll
    for (int p = 0; p < 16; p++) { accA[p] = 0ull; accB[p] = 0ull; }

    const int tA = tid;
    const int tB = tid + 128;

    #pragma unroll 1
    for (int dt = 0; dt < DCHUNK; dt += 32) {
        const int d0 = dbase + dt;
        __syncthreads();   // protect previous tile

        // Stage W tile: 32 x 33
        for (int idx = tid; idx < 32 * 33; idx += 128) {
            int dd = idx / 33, c = idx - dd * 33;
            float v;
            if (c < 16)      v = Wq[(d0 + dd) * 16 + c];
            else if (c < 32) v = Wk[(d0 + dd) * 16 + (c - 16)];
            else             v = Ww[d0 + dd];
            ws[dd][c] = v;
        }

        // Stage x tile transposed: 256 tokens x 32 d (coalesced LDG.128)
        {
            const int row_in_pass = tid >> 3;        // 0..15
            const int d4 = (tid & 7) * 4;            // 0..28
            #pragma unroll 4
            for (int pass = 0; pass < 16; pass++) {
                int tl = pass * 16 + row_in_pass;
                const float4 v = *reinterpret_cast<const float4*>(
                    &x[(size_t)(tok0 + tl) * DMODEL + d0 + d4]);
                xs[d4 + 0][tl] = v.x;
                xs[d4 + 1][tl] = v.y;
                xs[d4 + 2][tl] = v.z;
                xs[d4 + 3][tl] = v.w;
            }
        }
        __syncthreads();

        #pragma unroll 4
        for (int dd = 0; dd < 32; dd++) {
            const float xa = xs[dd][tA];
            const float xb = xs[dd][tB];
            const u64 xa2 = pack2(xa, xa);
            const u64 xb2 = pack2(xb, xb);
            #pragma unroll
            for (int p = 0; p < 16; p++) {
                const u64 wv = *reinterpret_cast<const u64*>(&ws[dd][2 * p]);
                accA[p] = fma2(xa2, wv, accA[p]);
                accB[p] = fma2(xb2, wv, accB[p]);
            }
            const float w32 = ws[dd][32];
            accwA = fmaf(xa, w32, accwA);
            accwB = fmaf(xb, w32, accwB);
        }
    }

    // Write partials
    float* pA = &g_part[((size_t)blockIdx.y * TOKENS + (tok0 + tA)) * NC];
    float* pB = &g_part[((size_t)blockIdx.y * TOKENS + (tok0 + tB)) * NC];
    #pragma unroll
    for (int p = 0; p < 16; p++) {
        float lo, hi;
        unpack2(accA[p], lo, hi); pA[2 * p] = lo; pA[2 * p + 1] = hi;
        unpack2(accB[p], lo, hi); pB[2 * p] = lo; pB[2 * p + 1] = hi;
    }
    pA[32] = accwA;
    pB[32] = accwB;
}

// ============================================================================
// Kernel 2: reduce D-split partials into Q / K / w buffers.
// ============================================================================
__global__ __launch_bounds__(256)
void reduce_kernel()
{
    int i = blockIdx.x * 256 + threadIdx.x;
    if (i >= TOKENS * NC) return;
    int tok = i / NC, c = i - tok * NC;
    float s = 0.f;
    #pragma unroll
    for (int r = 0; r < DSPLIT; r++)
        s += g_part[((size_t)r * TOKENS + tok) * NC + c];
    if (c < 16)      g_q[tok * 16 + c] = s;
    else if (c < 32) g_k[tok * 16 + (c - 16)] = s;
    else             g_w[tok] = s;
}

// ============================================================================
// Kernel 3: out[b,t,s] = relu(Q[b,t] . K[b,s]) * w[b,t]
// Grid: (64 s-tiles, 32 t-tiles, 4 batches). Block: 256 threads.
// Tile: 128 t x 64 s. Thread micro-tile: 8 t x 4 s, f32x2 accumulators.
// K fragment (4 rows x 16) held in registers; Q streamed from smem.
// ============================================================================
__global__ __launch_bounds__(256)
void dot_kernel(float* __restrict__ out)
{
    __shared__ float qs[128 * 16];   // Q tile [t][d]
    __shared__ float wts[128];

    const int tid = threadIdx.x;
    const int tt  = tid >> 4;        // 0..15 : t-thread
    const int st  = tid & 15;        // 0..15 : s-thread

    const int b     = blockIdx.z;
    const int tbase = blockIdx.y * 128;              // t tile origin
    const int sbase = blockIdx.x * 64;               // s tile origin
    const int tokq  = b * SEQ + tbase;               // global Q token base
    const int tokk  = b * SEQ + sbase;               // global K token base

    // Stage Q tile (128 x 16) and w
    #pragma unroll
    for (int p = 0; p < 2; p++) {
        int row = p * 64 + (tid >> 2);
        int c   = (tid & 3) * 4;
        *reinterpret_cast<float4*>(&qs[row * 16 + c]) =
            *reinterpret_cast<const float4*>(&g_q[(size_t)(tokq + row) * 16 + c]);
    }
    if (tid < 128) wts[tid] = g_w[tokq + tid];

    // K fragment: 4 rows of 16 floats -> 32 f32x2 in registers (L1/L2 hit)
    u64 kf[4][8];
    #pragma unroll
    for (int j = 0; j < 4; j++) {
        const float4* kp = reinterpret_cast<const float4*>(
            &g_k[(size_t)(tokk + st * 4 + j) * 16]);
        float4 v0 = kp[0], v1 = kp[1], v2 = kp[2], v3 = kp[3];
        kf[j][0] = pack2(v0.x, v0.y); kf[j][1] = pack2(v0.z, v0.w);
        kf[j][2] = pack2(v1.x, v1.y); kf[j][3] = pack2(v1.z, v1.w);
        kf[j][4] = pack2(v2.x, v2.y); kf[j][5] = pack2(v2.z, v2.w);
        kf[j][6] = pack2(v3.x, v3.y); kf[j][7] = pack2(v3.z, v3.w);
    }
    __syncthreads();

    u64 acc[8][4];
    #pragma unroll
    for (int i = 0; i < 8; i++)
        #pragma unroll
        for (int j = 0; j < 4; j++) acc[i][j] = 0ull;

    #pragma unroll
    for (int dp = 0; dp < 8; dp++) {
        u64 q2[8];
        #pragma unroll
        for (int i = 0; i < 8; i++)
            q2[i] = *reinterpret_cast<const u64*>(&qs[(tt + 16 * i) * 16 + 2 * dp]);
        #pragma unroll
        for (int i = 0; i < 8; i++)
            #pragma unroll
            for (int j = 0; j < 4; j++)
                acc[i][j] = fma2(q2[i], kf[j][dp], acc[i][j]);
    }

    // Epilogue: hadd halves, relu, * w[t], coalesced float4 stores
    #pragma unroll
    for (int i = 0; i < 8; i++) {
        const int t  = tbase + tt + 16 * i;
        const float wt = wts[tt + 16 * i];
        float lo, hi;
        float4 o;
        unpack2(acc[i][0], lo, hi); o.x = fmaxf(lo + hi, 0.f) * wt;
        unpack2(acc[i][1], lo, hi); o.y = fmaxf(lo + hi, 0.f) * wt;
        unpack2(acc[i][2], lo, hi); o.z = fmaxf(lo + hi, 0.f) * wt;
        unpack2(acc[i][3], lo, hi); o.w = fmaxf(lo + hi, 0.f) * wt;
        *reinterpret_cast<float4*>(
            &out[((size_t)(b * SEQ + t)) * SEQ + sbase + st * 4]) = o;
    }
}

// ============================================================================
extern "C" void kernel_launch(void* const* d_in, const int* in_sizes, int n_in,
                              void* d_out, int out_size)
{
    const float* x  = (const float*)d_in[0];
    const float* Wq = (const float*)d_in[1];
    const float* Wk = (const float*)d_in[2];
    const float* Ww = (const float*)d_in[3];
    float* out = (float*)d_out;

    proj_kernel<<<dim3(TOKENS / 256, DSPLIT), 128>>>(x, Wq, Wk, Ww);
    reduce_kernel<<<(TOKENS * NC + 255) / 256, 256>>>();
    dot_kernel<<<dim3(SEQ / 64, SEQ / 128, BATCH), 256>>>(out);
}

// round 5
// speedup vs baseline: 1.8385x; 1.8385x over previous
#include <cuda_runtime.h>
#include <cstdint>

// Problem constants
#define BATCH   4
#define SEQ     4096
#define DMODEL  2048
#define TOKENS  (BATCH * SEQ)     // 16384
#define NC      33                // 16 q + 16 k + 1 w
#define DSPLIT  8
#define DCHUNK  (DMODEL / DSPLIT) // 256

typedef unsigned long long u64;

// Scratch (static device globals: no dynamic allocation allowed)
__device__ float g_part[DSPLIT * TOKENS * NC];   // ~17.3 MB
__device__ float g_q[TOKENS * 16];
__device__ float g_k[TOKENS * 16];
__device__ float g_w[TOKENS];

// ---- packed f32x2 helpers (FFMA2 path, PTX-only on sm_103a) ----
__device__ __forceinline__ u64 pack2(float lo, float hi) {
    u64 r; asm("mov.b64 %0, {%1, %2};" : "=l"(r) : "f"(lo), "f"(hi)); return r;
}
__device__ __forceinline__ void unpack2(u64 v, float& lo, float& hi) {
    asm("mov.b64 {%0, %1}, %2;" : "=f"(lo), "=f"(hi) : "l"(v));
}
__device__ __forceinline__ u64 fma2(u64 a, u64 b, u64 c) {
    u64 d; asm("fma.rn.f32x2 %0, %1, %2, %3;" : "=l"(d) : "l"(a), "l"(b), "l"(c)); return d;
}

// ============================================================================
// Kernel 1: projection partials over a D chunk of x @ [Wq|Wk|Ww].
// Grid: (128 token-blocks, 8 D-splits) = 1024 blocks. Block: 128 threads,
// 128 tokens (1 per thread) -> ~58 regs -> 8 blocks/SM, 50% occupancy.
// ============================================================================
__global__ __launch_bounds__(128)
void proj_kernel(const float* __restrict__ x,
                 const float* __restrict__ Wq,
                 const float* __restrict__ Wk,
                 const float* __restrict__ Ww)
{
    __shared__ float xs[32][129];   // [d-sub][token], pad 129: conflict-free
    __shared__ float ws[32][34];    // [d-sub][33 cols], 8B rows

    const int tid   = threadIdx.x;
    const int tok0  = blockIdx.x * 128;
    const int dbase = blockIdx.y * DCHUNK;

    u64 acc[16];
    float accw = 0.f;
    #pragma unroll
    for (int p = 0; p < 16; p++) acc[p] = 0ull;

    const int rip = tid >> 3;        // 0..15 : token row within pass
    const int d4  = (tid & 7) * 4;   // 0..28 : d quad

    #pragma unroll 1
    for (int dt = 0; dt < DCHUNK; dt += 32) {
        const int d0 = dbase + dt;
        __syncthreads();   // protect previous tile

        // Stage W tile: 32 x 33
        for (int idx = tid; idx < 32 * 33; idx += 128) {
            int dd = idx / 33, c = idx - dd * 33;
            float v;
            if (c < 16)      v = Wq[(d0 + dd) * 16 + c];
            else if (c < 32) v = Wk[(d0 + dd) * 16 + (c - 16)];
            else             v = Ww[d0 + dd];
            ws[dd][c] = v;
        }

        // Stage x tile transposed: 128 tokens x 32 d (coalesced LDG.128)
        #pragma unroll
        for (int pass = 0; pass < 8; pass++) {
            int tl = pass * 16 + rip;
            const float4 v = *reinterpret_cast<const float4*>(
                &x[(size_t)(tok0 + tl) * DMODEL + d0 + d4]);
            xs[d4 + 0][tl] = v.x;
            xs[d4 + 1][tl] = v.y;
            xs[d4 + 2][tl] = v.z;
            xs[d4 + 3][tl] = v.w;
        }
        __syncthreads();

        #pragma unroll 4
        for (int dd = 0; dd < 32; dd++) {
            const float xa = xs[dd][tid];
            const u64 xa2 = pack2(xa, xa);
            #pragma unroll
            for (int p = 0; p < 16; p++) {
                const u64 wv = *reinterpret_cast<const u64*>(&ws[dd][2 * p]);
                acc[p] = fma2(xa2, wv, acc[p]);
            }
            accw = fmaf(xa, ws[dd][32], accw);
        }
    }

    float* pA = &g_part[((size_t)blockIdx.y * TOKENS + (tok0 + tid)) * NC];
    #pragma unroll
    for (int p = 0; p < 16; p++) {
        float lo, hi;
        unpack2(acc[p], lo, hi);
        pA[2 * p] = lo; pA[2 * p + 1] = hi;
    }
    pA[32] = accw;
}

// ============================================================================
// Kernel 2: reduce D-split partials into Q / K / w buffers.
// ============================================================================
__global__ __launch_bounds__(256)
void reduce_kernel()
{
    int i = blockIdx.x * 256 + threadIdx.x;
    if (i >= TOKENS * NC) return;
    int tok = i / NC, c = i - tok * NC;
    float s = 0.f;
    #pragma unroll
    for (int r = 0; r < DSPLIT; r++)
        s += g_part[((size_t)r * TOKENS + tok) * NC + c];
    if (c < 16)      g_q[tok * 16 + c] = s;
    else if (c < 32) g_k[tok * 16 + (c - 16)] = s;
    else             g_w[tok] = s;
}

// ============================================================================
// Kernel 3: out[b,t,s] = relu(Q[b,t] . K[b,s]) * w[b,t]
// Grid: (64 s-tiles, 64 t-tiles, 4 batches) = 16384 blocks. Block: 256 thr.
// Tile 64t x 64s; thread micro-tile 4t x 4s as 4t x 2 s-pairs of f32x2.
// Q duplicated into smem u64 (no inner-loop packing); K transposed in smem.
// acc = 8 u64 = 16 regs -> ~48 regs total -> 5 blocks/SM, ~60% occupancy.
// ============================================================================
__global__ __launch_bounds__(256)
void dot_kernel(float* __restrict__ out)
{
    __shared__ u64   qs2[64 * 16];  // [t][d], value duplicated in both halves
    __shared__ float kt[16][68];    // [d][s] transposed, padded row
    __shared__ float wts[64];

    const int tid = threadIdx.x;
    const int tt  = tid >> 4;        // 0..15 : t-thread
    const int st  = tid & 15;        // 0..15 : s-thread

    const int b     = blockIdx.z;
    const int tbase = blockIdx.y * 64;
    const int sbase = blockIdx.x * 64;
    const int tokq  = b * SEQ + tbase;
    const int tokk  = b * SEQ + sbase;

    // Stage Q tile duplicated (64 x 16 floats -> u64 pairs)
    {
        int row = tid >> 2, c = (tid & 3) * 4;
        const float4 v = *reinterpret_cast<const float4*>(
            &g_q[(size_t)(tokq + row) * 16 + c]);
        qs2[row * 16 + c + 0] = pack2(v.x, v.x);
        qs2[row * 16 + c + 1] = pack2(v.y, v.y);
        qs2[row * 16 + c + 2] = pack2(v.z, v.z);
        qs2[row * 16 + c + 3] = pack2(v.w, v.w);
    }
    // Stage K transposed (kt[d][s])
    {
        int r = tid >> 2, c = (tid & 3) * 4;
        const float4 v = *reinterpret_cast<const float4*>(
            &g_k[(size_t)(tokk + r) * 16 + c]);
        kt[c + 0][r] = v.x;
        kt[c + 1][r] = v.y;
        kt[c + 2][r] = v.z;
        kt[c + 3][r] = v.w;
    }
    if (tid < 64) wts[tid] = g_w[tokq + tid];
    __syncthreads();

    u64 acc[4][2];
    #pragma unroll
    for (int i = 0; i < 4; i++) { acc[i][0] = 0ull; acc[i][1] = 0ull; }

    #pragma unroll
    for (int d = 0; d < 16; d++) {
        const u64 k0 = *reinterpret_cast<const u64*>(&kt[d][st * 4 + 0]);
        const u64 k1 = *reinterpret_cast<const u64*>(&kt[d][st * 4 + 2]);
        #pragma unroll
        for (int i = 0; i < 4; i++) {
            const u64 q2 = qs2[(tt + 16 * i) * 16 + d];
            acc[i][0] = fma2(q2, k0, acc[i][0]);
            acc[i][1] = fma2(q2, k1, acc[i][1]);
        }
    }

    // Epilogue: relu, * w[t], coalesced float4 stores
    #pragma unroll
    for (int i = 0; i < 4; i++) {
        const int t = tbase + tt + 16 * i;
        const float wt = wts[tt + 16 * i];
        float lo, hi;
        float4 o;
        unpack2(acc[i][0], lo, hi);
        o.x = fmaxf(lo, 0.f) * wt;
        o.y = fmaxf(hi, 0.f) * wt;
        unpack2(acc[i][1], lo, hi);
        o.z = fmaxf(lo, 0.f) * wt;
        o.w = fmaxf(hi, 0.f) * wt;
        *reinterpret_cast<float4*>(
            &out[((size_t)(b * SEQ + t)) * SEQ + sbase + st * 4]) = o;
    }
}

// ============================================================================
extern "C" void kernel_launch(void* const* d_in, const int* in_sizes, int n_in,
                              void* d_out, int out_size)
{
    const float* x  = (const float*)d_in[0];
    const float* Wq = (const float*)d_in[1];
    const float* Wk = (const float*)d_in[2];
    const float* Ww = (const float*)d_in[3];
    float* out = (float*)d_out;

    proj_kernel<<<dim3(TOKENS / 128, DSPLIT), 128>>>(x, Wq, Wk, Ww);
    reduce_kernel<<<(TOKENS * NC + 255) / 256, 256>>>();
    dot_kernel<<<dim3(SEQ / 64, SEQ / 64, BATCH), 256>>>(out);
}

// round 6
// speedup vs baseline: 1.9216x; 1.0452x over previous
#include <cuda_runtime.h>
#include <cstdint>

// Problem constants
#define BATCH   4
#define SEQ     4096
#define DMODEL  2048
#define TOKENS  (BATCH * SEQ)     // 16384
#define NC      33                // 16 q + 16 k + 1 w
#define DSPLIT  8
#define DCHUNK  (DMODEL / DSPLIT) // 256

typedef unsigned long long u64;

// Scratch (static device globals: no dynamic allocation allowed)
__device__ float g_part[DSPLIT * TOKENS * NC];   // ~17.3 MB
__device__ float g_q[TOKENS * 16];
__device__ float g_k[TOKENS * 16];
__device__ float g_w[TOKENS];

// ---- packed f32x2 helpers (FFMA2 path, PTX-only on sm_103a) ----
__device__ __forceinline__ u64 pack2(float lo, float hi) {
    u64 r; asm("mov.b64 %0, {%1, %2};" : "=l"(r) : "f"(lo), "f"(hi)); return r;
}
__device__ __forceinline__ void unpack2(u64 v, float& lo, float& hi) {
    asm("mov.b64 {%0, %1}, %2;" : "=f"(lo), "=f"(hi) : "l"(v));
}
__device__ __forceinline__ u64 fma2(u64 a, u64 b, u64 c) {
    u64 d; asm("fma.rn.f32x2 %0, %1, %2, %3;" : "=l"(d) : "l"(a), "l"(b), "l"(c)); return d;
}

// ============================================================================
// Kernel 1: projection partials over a D chunk of x @ [Wq|Wk|Ww].
// Grid: (128 token-blocks, 8 D-splits) = 1024 blocks. Block: 128 threads,
// 1 token/thread. Software double-buffered staging: LDG tile t+1 into regs
// while computing tile t from smem; single __syncthreads per tile (reads and
// writes always target disjoint smem buffers within an iteration).
// ============================================================================
__global__ __launch_bounds__(128)
void proj_kernel(const float* __restrict__ x,
                 const float* __restrict__ Wq,
                 const float* __restrict__ Wk,
                 const float* __restrict__ Ww)
{
    __shared__ float xs[2][32][129];   // [buf][d-sub][token], pad: conflict-free
    __shared__ float ws[2][32][34];    // [buf][d-sub][33 cols]

    const int tid   = threadIdx.x;
    const int tok0  = blockIdx.x * 128;
    const int dbase = blockIdx.y * DCHUNK;

    const int rip = tid >> 3;        // 0..15 : token row within pass
    const int d4  = (tid & 7) * 4;   // 0..28 : d quad

    u64 acc[16];
    float accw = 0.f;
    #pragma unroll
    for (int p = 0; p < 16; p++) acc[p] = 0ull;

    float4 xr[8];
    float  wr[9];

    // ---- load tile (d0) into registers ----
    auto load_tile = [&](int d0) {
        #pragma unroll
        for (int pass = 0; pass < 8; pass++) {
            int tl = pass * 16 + rip;
            xr[pass] = *reinterpret_cast<const float4*>(
                &x[(size_t)(tok0 + tl) * DMODEL + d0 + d4]);
        }
        #pragma unroll
        for (int j = 0; j < 9; j++) {
            int idx = tid + j * 128;
            if (idx < 32 * 33) {
                int dd = idx / 33, c = idx - dd * 33;
                float v;
                if (c < 16)      v = Wq[(d0 + dd) * 16 + c];
                else if (c < 32) v = Wk[(d0 + dd) * 16 + (c - 16)];
                else             v = Ww[d0 + dd];
                wr[j] = v;
            }
        }
    };
    // ---- store registers into smem buffer ----
    auto store_tile = [&](int buf) {
        #pragma unroll
        for (int pass = 0; pass < 8; pass++) {
            int tl = pass * 16 + rip;
            xs[buf][d4 + 0][tl] = xr[pass].x;
            xs[buf][d4 + 1][tl] = xr[pass].y;
            xs[buf][d4 + 2][tl] = xr[pass].z;
            xs[buf][d4 + 3][tl] = xr[pass].w;
        }
        #pragma unroll
        for (int j = 0; j < 9; j++) {
            int idx = tid + j * 128;
            if (idx < 32 * 33) {
                int dd = idx / 33, c = idx - dd * 33;
                ws[buf][dd][c] = wr[j];
            }
        }
    };

    // prologue: stage tile 0 into buffer 0
    load_tile(dbase);
    store_tile(0);
    __syncthreads();

    #pragma unroll 2
    for (int t = 0; t < DCHUNK / 32; t++) {
        const int buf = t & 1;
        if (t < DCHUNK / 32 - 1)
            load_tile(dbase + (t + 1) * 32);   // in flight during compute

        #pragma unroll 8
        for (int dd = 0; dd < 32; dd++) {
            const float xa = xs[buf][dd][tid];
            const u64 xa2 = pack2(xa, xa);
            #pragma unroll
            for (int p = 0; p < 16; p++) {
                const u64 wv = *reinterpret_cast<const u64*>(&ws[buf][dd][2 * p]);
                acc[p] = fma2(xa2, wv, acc[p]);
            }
            accw = fmaf(xa, ws[buf][dd][32], accw);
        }

        if (t < DCHUNK / 32 - 1)
            store_tile(buf ^ 1);               // disjoint from compute buffer
        __syncthreads();
    }

    float* pA = &g_part[((size_t)blockIdx.y * TOKENS + (tok0 + tid)) * NC];
    #pragma unroll
    for (int p = 0; p < 16; p++) {
        float lo, hi;
        unpack2(acc[p], lo, hi);
        pA[2 * p] = lo; pA[2 * p + 1] = hi;
    }
    pA[32] = accw;
}

// ============================================================================
// Kernel 2: reduce D-split partials into Q / K / w buffers.
// ============================================================================
__global__ __launch_bounds__(256)
void reduce_kernel()
{
    int i = blockIdx.x * 256 + threadIdx.x;
    if (i >= TOKENS * NC) return;
    int tok = i / NC, c = i - tok * NC;
    float s = 0.f;
    #pragma unroll
    for (int r = 0; r < DSPLIT; r++)
        s += g_part[((size_t)r * TOKENS + tok) * NC + c];
    if (c < 16)      g_q[tok * 16 + c] = s;
    else if (c < 32) g_k[tok * 16 + (c - 16)] = s;
    else             g_w[tok] = s;
}

// ============================================================================
// Kernel 3: out[b,t,s] = relu(Q[b,t] . K[b,s]) * w[b,t]
// Grid: (16 s-supertiles, 64 t-tiles, 4 batches) = 4096 blocks, 256 threads.
// Block covers 64t x 256s: Q tile staged once (reused 4x), K subtiles
// double-buffered through registers+smem, one sync per subtile.
// Thread micro-tile 4t x 4s as f32x2 s-pairs.
// ============================================================================
__global__ __launch_bounds__(256)
void dot_kernel(float* __restrict__ out)
{
    __shared__ u64   qs2[64 * 17];   // [t][d] value-duplicated pairs, padded
    __shared__ float kt[2][16][68];  // [buf][d][s] transposed, padded
    __shared__ float wts[64];

    const int tid = threadIdx.x;
    const int tt  = tid >> 4;        // 0..15 : t-thread
    const int st  = tid & 15;        // 0..15 : s-thread

    const int b      = blockIdx.z;
    const int tbase  = blockIdx.y * 64;
    const int sbase0 = blockIdx.x * 256;
    const int tokq   = b * SEQ + tbase;
    const int tokk0  = b * SEQ + sbase0;

    const int srow = tid >> 2;           // 0..63
    const int scol = (tid & 3) * 4;      // 0,4,8,12

    // Stage Q tile duplicated (64 x 16 floats -> u64 pairs) + w
    {
        const float4 v = *reinterpret_cast<const float4*>(
            &g_q[(size_t)(tokq + srow) * 16 + scol]);
        qs2[srow * 17 + scol + 0] = pack2(v.x, v.x);
        qs2[srow * 17 + scol + 1] = pack2(v.y, v.y);
        qs2[srow * 17 + scol + 2] = pack2(v.z, v.z);
        qs2[srow * 17 + scol + 3] = pack2(v.w, v.w);
    }
    if (tid < 64) wts[tid] = g_w[tokq + tid];

    // Prefetch + stage K subtile 0 into buffer 0
    float4 kv = *reinterpret_cast<const float4*>(
        &g_k[(size_t)(tokk0 + srow) * 16 + scol]);
    kt[0][scol + 0][srow] = kv.x;
    kt[0][scol + 1][srow] = kv.y;
    kt[0][scol + 2][srow] = kv.z;
    kt[0][scol + 3][srow] = kv.w;
    __syncthreads();

    #pragma unroll
    for (int ss = 0; ss < 4; ss++) {
        const int buf = ss & 1;
        if (ss < 3)
            kv = *reinterpret_cast<const float4*>(
                &g_k[(size_t)(tokk0 + (ss + 1) * 64 + srow) * 16 + scol]);

        u64 acc[4][2];
        #pragma unroll
        for (int i = 0; i < 4; i++) { acc[i][0] = 0ull; acc[i][1] = 0ull; }

        #pragma unroll
        for (int d = 0; d < 16; d++) {
            const u64 k0 = *reinterpret_cast<const u64*>(&kt[buf][d][st * 4 + 0]);
            const u64 k1 = *reinterpret_cast<const u64*>(&kt[buf][d][st * 4 + 2]);
            #pragma unroll
            for (int i = 0; i < 4; i++) {
                const u64 q2 = qs2[(tt + 16 * i) * 17 + d];
                acc[i][0] = fma2(q2, k0, acc[i][0]);
                acc[i][1] = fma2(q2, k1, acc[i][1]);
            }
        }

        // Epilogue: relu, * w[t], coalesced float4 stores
        const int sbase = sbase0 + ss * 64;
        #pragma unroll
        for (int i = 0; i < 4; i++) {
            const int t = tbase + tt + 16 * i;
            const float wt = wts[tt + 16 * i];
            float lo, hi;
            float4 o;
            unpack2(acc[i][0], lo, hi);
            o.x = fmaxf(lo, 0.f) * wt;
            o.y = fmaxf(hi, 0.f) * wt;
            unpack2(acc[i][1], lo, hi);
            o.z = fmaxf(lo, 0.f) * wt;
            o.w = fmaxf(hi, 0.f) * wt;
            *reinterpret_cast<float4*>(
                &out[((size_t)(b * SEQ + t)) * SEQ + sbase + st * 4]) = o;
        }

        if (ss < 3) {   // stage next subtile into the other buffer
            kt[buf ^ 1][scol + 0][srow] = kv.x;
            kt[buf ^ 1][scol + 1][srow] = kv.y;
            kt[buf ^ 1][scol + 2][srow] = kv.z;
            kt[buf ^ 1][scol + 3][srow] = kv.w;
        }
        __syncthreads();
    }
}

// ============================================================================
extern "C" void kernel_launch(void* const* d_in, const int* in_sizes, int n_in,
                              void* d_out, int out_size)
{
    const float* x  = (const float*)d_in[0];
    const float* Wq = (const float*)d_in[1];
    const float* Wk = (const float*)d_in[2];
    const float* Ww = (const float*)d_in[3];
    float* out = (float*)d_out;

    proj_kernel<<<dim3(TOKENS / 128, DSPLIT), 128>>>(x, Wq, Wk, Ww);
    reduce_kernel<<<(TOKENS * NC + 255) / 256, 256>>>();
    dot_kernel<<<dim3(SEQ / 256, SEQ / 64, BATCH), 256>>>(out);
}

// round 9
// speedup vs baseline: 2.1515x; 1.1196x over previous
#include <cuda_runtime.h>
#include <cstdint>

// Problem constants
#define BATCH   4
#define SEQ     4096
#define DMODEL  2048
#define TOKENS  (BATCH * SEQ)     // 16384
#define NCPAD   36                // 16 q + 16 k + w + 3 pad (float4-aligned pitch)
#define DSPLIT  8
#define DCHUNK  (DMODEL / DSPLIT) // 256

typedef unsigned long long u64;

// Scratch (static device globals: no dynamic allocation allowed)
__device__ float g_part[(size_t)DSPLIT * TOKENS * NCPAD];   // ~18.9 MB
__device__ float g_q[TOKENS * 16];
__device__ float g_k[TOKENS * 16];
__device__ float g_w[TOKENS];

// ---- packed f32x2 helpers (FFMA2 path, PTX-only on sm_103a) ----
__device__ __forceinline__ u64 pack2(float lo, float hi) {
    u64 r; asm("mov.b64 %0, {%1, %2};" : "=l"(r) : "f"(lo), "f"(hi)); return r;
}
__device__ __forceinline__ void unpack2(u64 v, float& lo, float& hi) {
    asm("mov.b64 {%0, %1}, %2;" : "=f"(lo), "=f"(hi) : "l"(v));
}
__device__ __forceinline__ u64 fma2(u64 a, u64 b, u64 c) {
    u64 d; asm("fma.rn.f32x2 %0, %1, %2, %3;" : "=l"(d) : "l"(a), "l"(b), "l"(c)); return d;
}

// ============================================================================
// Kernel 1: projection partials. Grid (DSPLIT, 64 token-blocks) = 512 blocks.
// Block: 128 threads, 2 tokens/thread (256 tokens). W chunk (256 x 36) staged
// ONCE in smem (one sync total); x rows loaded straight to registers
// (64B contiguous per token per d-tile). Inner mix per k:
// 8 LDS.128 + 1 LDS.64 + 2 MOV + 34 FFMA2  -> 76% fma density.
// ============================================================================
__global__ __launch_bounds__(128)
void proj_kernel(const float* __restrict__ x,
                 const float* __restrict__ Wq,
                 const float* __restrict__ Wk,
                 const float* __restrict__ Ww)
{
    __shared__ float ws[DCHUNK][NCPAD];   // 36 KB

    const int tid   = threadIdx.x;
    const int dbase = blockIdx.x * DCHUNK;
    const int tok0  = blockIdx.y * 256;
    const int t0    = tok0 + 2 * tid;
    const int t1    = t0 + 1;

    // ---- stage W chunk: Wq -> cols 0-15, Wk -> 16-31, Ww -> 32, 33-35 = 0 ----
    #pragma unroll
    for (int i = 0; i < 8; i++) {
        int task = tid + 128 * i;
        int row = task >> 2, q = (task & 3) * 4;
        *reinterpret_cast<float4*>(&ws[row][q]) =
            *reinterpret_cast<const float4*>(&Wq[(size_t)(dbase + row) * 16 + q]);
    }
    #pragma unroll
    for (int i = 0; i < 8; i++) {
        int task = tid + 128 * i;
        int row = task >> 2, q = (task & 3) * 4;
        *reinterpret_cast<float4*>(&ws[row][16 + q]) =
            *reinterpret_cast<const float4*>(&Wk[(size_t)(dbase + row) * 16 + q]);
    }
    #pragma unroll
    for (int i = 0; i < 2; i++) {
        int row = tid + 128 * i;
        ws[row][32] = Ww[dbase + row];
        ws[row][33] = 0.f; ws[row][34] = 0.f; ws[row][35] = 0.f;
    }
    __syncthreads();

    u64 acc0[17], acc1[17];
    #pragma unroll
    for (int p = 0; p < 17; p++) { acc0[p] = 0ull; acc1[p] = 0ull; }

    const float* x0 = &x[(size_t)t0 * DMODEL + dbase];
    const float* x1 = &x[(size_t)t1 * DMODEL + dbase];

    #pragma unroll 1
    for (int dt = 0; dt < DCHUNK; dt += 16) {
        float4 xa[4], xb[4];
        #pragma unroll
        for (int j = 0; j < 4; j++) {
            xa[j] = *reinterpret_cast<const float4*>(x0 + dt + 4 * j);
            xb[j] = *reinterpret_cast<const float4*>(x1 + dt + 4 * j);
        }
        #pragma unroll
        for (int k = 0; k < 16; k++) {
            const float v0 = reinterpret_cast<const float*>(xa)[k];
            const float v1 = reinterpret_cast<const float*>(xb)[k];
            const u64 xd0 = pack2(v0, v0);
            const u64 xd1 = pack2(v1, v1);
            const int dd = dt + k;
            #pragma unroll
            for (int q = 0; q < 8; q++) {
                const ulonglong2 wv =
                    *reinterpret_cast<const ulonglong2*>(&ws[dd][4 * q]);
                acc0[2 * q]     = fma2(xd0, wv.x, acc0[2 * q]);
                acc0[2 * q + 1] = fma2(xd0, wv.y, acc0[2 * q + 1]);
                acc1[2 * q]     = fma2(xd1, wv.x, acc1[2 * q]);
                acc1[2 * q + 1] = fma2(xd1, wv.y, acc1[2 * q + 1]);
            }
            const u64 w16 = *reinterpret_cast<const u64*>(&ws[dd][32]);
            acc0[16] = fma2(xd0, w16, acc0[16]);
            acc1[16] = fma2(xd1, w16, acc1[16]);
        }
    }

    // Write partials (bit patterns are the floats; no unpack needed)
    float* p0 = &g_part[((size_t)blockIdx.x * TOKENS + t0) * NCPAD];
    float* p1 = &g_part[((size_t)blockIdx.x * TOKENS + t1) * NCPAD];
    #pragma unroll
    for (int q = 0; q < 8; q++) {
        ulonglong2 v0; v0.x = acc0[2 * q]; v0.y = acc0[2 * q + 1];
        ulonglong2 v1; v1.x = acc1[2 * q]; v1.y = acc1[2 * q + 1];
        *reinterpret_cast<ulonglong2*>(&p0[4 * q]) = v0;
        *reinterpret_cast<ulonglong2*>(&p1[4 * q]) = v1;
    }
    *reinterpret_cast<u64*>(&p0[32]) = acc0[16];
    *reinterpret_cast<u64*>(&p1[32]) = acc1[16];
}

// ============================================================================
// Kernel 2: reduce D-split partials (float4-vectorized, 9 quads/token).
// ============================================================================
__global__ __launch_bounds__(256)
void reduce_kernel()
{
    int i = blockIdx.x * 256 + threadIdx.x;   // 0 .. 16384*9-1
    int tok = i / 9, c4 = i - tok * 9;
    float4 s = make_float4(0.f, 0.f, 0.f, 0.f);
    #pragma unroll
    for (int r = 0; r < DSPLIT; r++) {
        const float4 v = *reinterpret_cast<const float4*>(
            &g_part[((size_t)r * TOKENS + tok) * NCPAD + 4 * c4]);
        s.x += v.x; s.y += v.y; s.z += v.z; s.w += v.w;
    }
    if (c4 < 4)
        *reinterpret_cast<float4*>(&g_q[tok * 16 + 4 * c4]) = s;
    else if (c4 < 8)
        *reinterpret_cast<float4*>(&g_k[tok * 16 + 4 * (c4 - 4)]) = s;
    else
        g_w[tok] = s.x;
}

// ============================================================================
// Kernel 3: out[b,t,s] = relu(Q[b,t] . K[b,s]) * w[b,t]
// Grid (32 s-tiles, 32 t-tiles, 4) = 4096 blocks, 256 threads.
// Tile 128t x 128s, micro-tile 8t x 8s (s-pairs in f32x2).
// Per d: 2 LDS.128 (K, bank-swizzled) + 8 LDS.64 (Q dup) + 32 FFMA2.
// ============================================================================

// kt column swizzle: spreads the 32B-strided LDS.128 across all bank groups.
__device__ __forceinline__ int kt_col(int s) {
    int st = s >> 3;
    return 8 * st + 4 * (st >> 2) + (s & 7);
}

__global__ __launch_bounds__(256)
void dot_kernel(float* __restrict__ out)
{
    __shared__ u64   qs2[128][17];   // [t][d] value-duplicated pairs (17.4 KB)
    __shared__ float kt[16][148];    // [d][s] transposed, swizzled (9.5 KB)
    __shared__ float wts[128];

    const int tid = threadIdx.x;
    const int tt  = tid >> 4;        // 0..15 : t-thread
    const int st  = tid & 15;        // 0..15 : s-thread (8 s each)

    const int b     = blockIdx.z;
    const int tbase = blockIdx.y * 128;
    const int sbase = blockIdx.x * 128;
    const int tokq  = b * SEQ + tbase;
    const int tokk  = b * SEQ + sbase;

    // Stage Q tile duplicated: 128 rows x 16 -> u64 dup pairs
    #pragma unroll
    for (int i = 0; i < 2; i++) {
        int task = tid + 256 * i;
        int row = task >> 2, q = (task & 3) * 4;
        const float4 v = *reinterpret_cast<const float4*>(
            &g_q[(size_t)(tokq + row) * 16 + q]);
        qs2[row][q + 0] = pack2(v.x, v.x);
        qs2[row][q + 1] = pack2(v.y, v.y);
        qs2[row][q + 2] = pack2(v.z, v.z);
        qs2[row][q + 3] = pack2(v.w, v.w);
    }
    // Stage K transposed + swizzled: kt[d][col(s)] = K[s][d]
    #pragma unroll
    for (int i = 0; i < 2; i++) {
        int task = tid + 256 * i;
        int s = task >> 2, q = (task & 3) * 4;
        const float4 v = *reinterpret_cast<const float4*>(
            &g_k[(size_t)(tokk + s) * 16 + q]);
        const int c = kt_col(s);
        kt[q + 0][c] = v.x;
        kt[q + 1][c] = v.y;
        kt[q + 2][c] = v.z;
        kt[q + 3][c] = v.w;
    }
    if (tid < 128) wts[tid] = g_w[tokq + tid];
    __syncthreads();

    const int c0 = 8 * st + 4 * (st >> 2);   // this thread's kt column base

    u64 acc[8][4];
    #pragma unroll
    for (int i = 0; i < 8; i++)
        #pragma unroll
        for (int j = 0; j < 4; j++) acc[i][j] = 0ull;

    #pragma unroll
    for (int d = 0; d < 16; d++) {
        const ulonglong2 ka = *reinterpret_cast<const ulonglong2*>(&kt[d][c0]);
        const ulonglong2 kb = *reinterpret_cast<const ulonglong2*>(&kt[d][c0 + 4]);
        #pragma unroll
        for (int i = 0; i < 8; i++) {
            const u64 q2 = qs2[tt + 16 * i][d];
            acc[i][0] = fma2(q2, ka.x, acc[i][0]);
            acc[i][1] = fma2(q2, ka.y, acc[i][1]);
            acc[i][2] = fma2(q2, kb.x, acc[i][2]);
            acc[i][3] = fma2(q2, kb.y, acc[i][3]);
        }
    }

    // Epilogue: relu, * w[t], 2x STG.128 per row
    #pragma unroll
    for (int i = 0; i < 8; i++) {
        const int t = tbase + tt + 16 * i;
        const float wt = wts[tt + 16 * i];
        float lo, hi;
        float4 oa, ob;
        unpack2(acc[i][0], lo, hi);
        oa.x = fmaxf(lo, 0.f) * wt;  oa.y = fmaxf(hi, 0.f) * wt;
        unpack2(acc[i][1], lo, hi);
        oa.z = fmaxf(lo, 0.f) * wt;  oa.w = fmaxf(hi, 0.f) * wt;
        unpack2(acc[i][2], lo, hi);
        ob.x = fmaxf(lo, 0.f) * wt;  ob.y = fmaxf(hi, 0.f) * wt;
        unpack2(acc[i][3], lo, hi);
        ob.z = fmaxf(lo, 0.f) * wt;  ob.w = fmaxf(hi, 0.f) * wt;
        float* o = &out[((size_t)(b * SEQ + t)) * SEQ + sbase + st * 8];
        *reinterpret_cast<float4*>(o)     = oa;
        *reinterpret_cast<float4*>(o + 4) = ob;
    }
}

// ============================================================================
extern "C" void kernel_launch(void* const* d_in, const int* in_sizes, int n_in,
                              void* d_out, int out_size)
{
    const float* x  = (const float*)d_in[0];
    const float* Wq = (const float*)d_in[1];
    const float* Wk = (const float*)d_in[2];
    const float* Ww = (const float*)d_in[3];
    float* out = (float*)d_out;

    proj_kernel<<<dim3(DSPLIT, TOKENS / 256), 128>>>(x, Wq, Wk, Ww);
    reduce_kernel<<<(TOKENS * 9) / 256, 256>>>();
    dot_kernel<<<dim3(SEQ / 128, SEQ / 128, BATCH), 256>>>(out);
}